// round 9
// baseline (speedup 1.0000x reference)
#include <cuda_runtime.h>
#include <math.h>

#define Bz 64
#define Tz 512
#define Hz 1024
#define H2z 2048
#define NCTA 256
#define NS1 32             // GEMM1 k-slices (K=32)
#define NS2 16             // GEMM2 k-slices (K=64)

// Scratch (__device__ globals; no allocation allowed)
__device__ float g_xw[(size_t)32768 * 1024];   // [B*T, H]
__device__ float g_h[Bz * Hz];
__device__ float g_hrnn[Bz * Hz];
__device__ float g_p1[NS1 * Bz * Hz];          // 8 MB
__device__ float g_p2[NS2 * Bz * H2z];         // 8 MB
__device__ float g_lpp[Bz][4];
__device__ unsigned g_count, g_gen;

typedef unsigned long long ull;
__device__ __forceinline__ ull dup2(float a) {
    ull r; asm("mov.b64 %0,{%1,%1};" : "=l"(r) : "f"(a)); return r;
}
__device__ __forceinline__ void fma2(ull& acc, ull a, ull w) {
    asm("fma.rn.f32x2 %0,%1,%2,%0;" : "+l"(acc) : "l"(a), "l"(w));
}

// Atomic-counter grid barrier (proven R3/R7/R8 design), 256 arrivals.
__device__ __forceinline__ void grid_sync() {
    __syncthreads();
    if (threadIdx.x == 0) {
        unsigned g = *(volatile unsigned*)&g_gen;
        __threadfence();
        unsigned old = atomicAdd(&g_count, 1u);
        if (old == NCTA - 1) {
            g_count = 0u;
            __threadfence();
            atomicAdd(&g_gen, 1u);
        } else {
            while (*(volatile unsigned*)&g_gen == g) { }
        }
        __threadfence();
    }
    __syncthreads();
}

// Persistent-kernel SMEM (~65 KB): resident weight slices + A staging
struct SmemR {
    float As[64][66];      // staged A, [k][row]
    float Ws1[32][130];    // w_hh slice, [k][n]
    float Ws2[64][130];    // w_g  slice, [k][n]
    float red[8];
};

struct SmemX {             // xw kernel staging (R7/R8 verbatim)
    float As[32][66];
    float Ws[32][130];
};

// Stage A[64][kcnt] (row-major [64][1024] global, k-window kb) into As.
__device__ __forceinline__ void stage_A(float (*As)[66],
    const float* __restrict__ A, int kb, int kcnt)
{
    const int tid = threadIdx.x;
    const int row = tid >> 2;
    const int cb = (tid & 3) * (kcnt >> 2);
    for (int c = 0; c < (kcnt >> 2); c += 4) {
        float4 v = __ldcg((const float4*)&A[row * 1024 + kb + cb + c]);
        As[cb + c + 0][row] = v.x;
        As[cb + c + 1][row] = v.y;
        As[cb + c + 2][row] = v.z;
        As[cb + c + 3][row] = v.w;
    }
}

// Inner GEMM on resident SMEM operands (proven core, verbatim).
__device__ __forceinline__ void gemm_resident(
    const float (*As)[66], const float (*Ws)[130], int kcnt, ull acc[4][4])
{
    const int tid = threadIdx.x;
    const int tx = tid & 15;
    const int ty4 = (tid >> 4) << 2;
    #pragma unroll 8
    for (int k = 0; k < kcnt; k++) {
        float2 a01 = *(const float2*)&As[k][ty4];
        float2 a23 = *(const float2*)&As[k][ty4 + 2];
        ull ad0 = dup2(a01.x), ad1 = dup2(a01.y);
        ull ad2 = dup2(a23.x), ad3 = dup2(a23.y);
        ull w_[4];
        #pragma unroll
        for (int m = 0; m < 4; m++)
            w_[m] = *(const ull*)&Ws[k][m * 32 + tx * 2];
        #pragma unroll
        for (int m = 0; m < 4; m++) {
            fma2(acc[0][m], ad0, w_[m]);
            fma2(acc[1][m], ad1, w_[m]);
            fma2(acc[2][m], ad2, w_[m]);
            fma2(acc[3][m], ad3, w_[m]);
        }
    }
}

__device__ __forceinline__ void store_tile(float* __restrict__ Cp, int ldC,
                                           int n0, ull acc[4][4])
{
    const int tid = threadIdx.x;
    const int tx = tid & 15;
    const int ty4 = (tid >> 4) << 2;
    #pragma unroll
    for (int i = 0; i < 4; i++) {
        int b = ty4 + i;
        #pragma unroll
        for (int m = 0; m < 4; m++)
            *(float2*)&Cp[(size_t)b * ldC + n0 + m * 32 + tx * 2] =
                *(float2*)&acc[i][m];
    }
}

// ---------------------------------------------------------------------------
// Precompute: g_xw = x @ w_ih^T + b_ih + b_hh (R7/R8 verbatim)
// ---------------------------------------------------------------------------
__global__ __launch_bounds__(256) void xw_kernel(
    const float* __restrict__ x, const float* __restrict__ w_ih,
    const float* __restrict__ b_ih, const float* __restrict__ b_hh)
{
    __shared__ SmemX s;
    const int n0 = blockIdx.x * 128;
    const int m0 = blockIdx.y * 64;
    const int tid = threadIdx.x;
    const int tx = tid & 15;
    const int ty4 = (tid >> 4) << 2;
    ull acc[4][4] = {};

    const float* A = x + (size_t)m0 * 1024;
    const float* W = w_ih + (size_t)n0 * 1024;
    for (int k0 = 0; k0 < 1024; k0 += 32) {
        #pragma unroll
        for (int i = 0; i < 8; i++) {
            int e = tid + i * 256;
            int row = e >> 5, kk = e & 31;
            s.As[kk][row] = __ldg(&A[row * 1024 + k0 + kk]);
        }
        #pragma unroll
        for (int i = 0; i < 16; i++) {
            int e = tid + i * 256;
            int n = e >> 5, kk = e & 31;
            s.Ws[kk][n] = __ldg(&W[n * 1024 + k0 + kk]);
        }
        __syncthreads();
        #pragma unroll 8
        for (int k = 0; k < 32; k++) {
            float2 a01 = *(const float2*)&s.As[k][ty4];
            float2 a23 = *(const float2*)&s.As[k][ty4 + 2];
            ull ad0 = dup2(a01.x), ad1 = dup2(a01.y);
            ull ad2 = dup2(a23.x), ad3 = dup2(a23.y);
            ull w_[4];
            #pragma unroll
            for (int m = 0; m < 4; m++)
                w_[m] = *(const ull*)&s.Ws[k][m * 32 + tx * 2];
            #pragma unroll
            for (int m = 0; m < 4; m++) {
                fma2(acc[0][m], ad0, w_[m]);
                fma2(acc[1][m], ad1, w_[m]);
                fma2(acc[2][m], ad2, w_[m]);
                fma2(acc[3][m], ad3, w_[m]);
            }
        }
        __syncthreads();
    }
    #pragma unroll
    for (int i = 0; i < 4; i++) {
        size_t m = m0 + ty4 + i;
        #pragma unroll
        for (int m4 = 0; m4 < 4; m4++) {
            int n = n0 + m4 * 32 + tx * 2;
            float2 v = *(float2*)&acc[i][m4];
            v.x += __ldg(&b_ih[n])     + __ldg(&b_hh[n]);
            v.y += __ldg(&b_ih[n + 1]) + __ldg(&b_hh[n + 1]);
            *(float2*)&g_xw[m * Hz + n] = v;
        }
    }
}

// ---------------------------------------------------------------------------
// Persistent recurrent kernel: 512 steps, 256 CTAs x 256 threads, 2 CTAs/SM.
// GEMM1: 8 n-tiles(128) x 32 sl(K=32).  GEMM2: 16 n-tiles(128) x 16 sl(K=64).
// ---------------------------------------------------------------------------
__global__ __launch_bounds__(256, 2) void rnn_persistent(
    const float* __restrict__ eps, const float* __restrict__ w_hh,
    const float* __restrict__ w_g, const float* __restrict__ b_g,
    float* __restrict__ o_seq, float* __restrict__ o_prob,
    float* __restrict__ o_mu, float* __restrict__ o_std)
{
    extern __shared__ unsigned char smraw[];
    SmemR& sm = *(SmemR*)smraw;
    const int cta = blockIdx.x;
    const int tid = threadIdx.x;
    const float LPC = -0.5f * 1.8378770664093453f * (float)Hz;

    const int n01 = (cta & 7)  * 128, kb1 = (cta >> 3) * 32;   // GEMM1 tile
    const int n02 = (cta & 15) * 128, kb2 = (cta >> 4) * 64;   // GEMM2 tile
    const size_t p1off = (size_t)(cta >> 3) * (Bz * Hz);
    const size_t p2off = (size_t)(cta >> 4) * (Bz * H2z);

    // zero recurrent state: 65536 elems / 65536 threads
    g_h[cta * 256 + tid] = 0.0f;

    // preload resident weight slices (coalesced along k; once per launch)
    for (int e = tid; e < 128 * 32; e += 256) {
        int k = e & 31, n = e >> 5;
        sm.Ws1[k][n] = __ldg(&w_hh[(size_t)(n01 + n) * 1024 + kb1 + k]);
    }
    for (int e = tid; e < 128 * 64; e += 256) {
        int k = e & 63, n = e >> 6;
        sm.Ws2[k][n] = __ldg(&w_g[(size_t)(n02 + n) * 1024 + kb2 + k]);
    }
    grid_sync();

    for (int t = 0; t < Tz; t++) {
        // ---- P0: o_prob(t-1) + GEMM1 partial: g_p1 = h @ w_hh^T -----------
        if (t > 0 && cta < Bz && tid == 0) {
            float s0 = __ldcg(&g_lpp[cta][0]) + __ldcg(&g_lpp[cta][1]);
            float s1 = __ldcg(&g_lpp[cta][2]) + __ldcg(&g_lpp[cta][3]);
            o_prob[cta * Tz + (t - 1)] = s0 + s1 + LPC;
        }
        stage_A(sm.As, g_h, kb1, 32);
        __syncthreads();
        {
            ull acc[4][4] = {};
            gemm_resident(sm.As, sm.Ws1, 32, acc);
            store_tile(g_p1 + p1off, Hz, n01, acc);
        }
        grid_sync();

        // ---- P1: combine 32 partials + xw + tanh -> g_hrnn (1 elem/thr) ---
        {
            int idx = cta * 256 + tid;               // b*1024 + j
            int b = idx >> 10, j = idx & 1023;
            float v0 = __ldg(&g_xw[((size_t)b * Tz + t) * Hz + j]);
            float v1 = 0.f, v2 = 0.f, v3 = 0.f;
            #pragma unroll
            for (int sl = 0; sl < NS1; sl += 4) {
                v0 += __ldcg(&g_p1[(size_t)(sl + 0) * (Bz * Hz) + idx]);
                v1 += __ldcg(&g_p1[(size_t)(sl + 1) * (Bz * Hz) + idx]);
                v2 += __ldcg(&g_p1[(size_t)(sl + 2) * (Bz * Hz) + idx]);
                v3 += __ldcg(&g_p1[(size_t)(sl + 3) * (Bz * Hz) + idx]);
            }
            g_hrnn[idx] = tanhf((v0 + v1) + (v2 + v3));
        }
        grid_sync();

        // ---- P2: GEMM2 partial: g_p2 = h_rnn @ w_g^T ----------------------
        stage_A(sm.As, g_hrnn, kb2, 64);
        __syncthreads();
        {
            ull acc[4][4] = {};
            gemm_resident(sm.As, sm.Ws2, 64, acc);
            store_tile(g_p2 + p2off, H2z, n02, acc);
        }
        grid_sync();

        // ---- P3: epilogue, quarter batch-row per CTA (1 j/thread) ---------
        {
            const int b = cta >> 2;
            const int j = (cta & 3) * 256 + tid;
            float ss = __ldg(&b_g[j]);
            float mu = __ldg(&b_g[Hz + j]);
            #pragma unroll
            for (int sl = 0; sl < NS2; sl++) {
                const float* p = g_p2 + (size_t)sl * (Bz * H2z) + (size_t)b * H2z;
                ss += __ldcg(&p[j]);
                mu += __ldcg(&p[Hz + j]);
            }
            float sd = (ss > 20.f) ? ss : log1pf(__expf(ss));
            float e = __ldg(&eps[((size_t)b * Tz + t) * Hz + j]);
            float smp = mu + sd * e;
            size_t o = ((size_t)b * Tz + t) * Hz + j;
            o_seq[o] = smp;
            o_mu[o]  = mu;
            o_std[o] = sd;
            g_h[b * Hz + j] = smp;

            float lp = -0.5f * e * e - __logf(sd);
            #pragma unroll
            for (int off = 16; off > 0; off >>= 1)
                lp += __shfl_xor_sync(0xffffffffu, lp, off);
            if ((tid & 31) == 0) sm.red[tid >> 5] = lp;
            __syncthreads();
            if (tid == 0) {
                float sum = 0.0f;
                #pragma unroll
                for (int w = 0; w < 8; w++) sum += sm.red[w];
                g_lpp[b][cta & 3] = sum;
            }
        }
        grid_sync();
    }

    // final o_prob for t = 511
    if (cta < Bz && tid == 0) {
        float s0 = __ldcg(&g_lpp[cta][0]) + __ldcg(&g_lpp[cta][1]);
        float s1 = __ldcg(&g_lpp[cta][2]) + __ldcg(&g_lpp[cta][3]);
        o_prob[cta * Tz + (Tz - 1)] = s0 + s1 + LPC;
    }
}

// ---------------------------------------------------------------------------
extern "C" void kernel_launch(void* const* d_in, const int* in_sizes, int n_in,
                              void* d_out, int out_size)
{
    const float* x    = (const float*)d_in[0];
    const float* eps  = (const float*)d_in[1];
    const float* w_ih = (const float*)d_in[2];
    const float* w_hh = (const float*)d_in[3];
    const float* b_ih = (const float*)d_in[4];
    const float* b_hh = (const float*)d_in[5];
    const float* w_g  = (const float*)d_in[6];
    const float* b_g  = (const float*)d_in[7];

    float* out = (float*)d_out;
    float* o_seq  = out;
    float* o_prob = out + (size_t)Bz * Tz * Hz;
    float* o_mu   = o_prob + (size_t)Bz * Tz;
    float* o_std  = o_mu + (size_t)Bz * Tz * Hz;

    cudaFuncSetAttribute(rnn_persistent,
                         cudaFuncAttributeMaxDynamicSharedMemorySize,
                         (int)sizeof(SmemR));

    xw_kernel<<<dim3(8, 512), 256>>>(x, w_ih, b_ih, b_hh);
    rnn_persistent<<<NCTA, 256, sizeof(SmemR)>>>(eps, w_hh, w_g, b_g,
                                                 o_seq, o_prob, o_mu, o_std);
}